// round 9
// baseline (speedup 1.0000x reference)
#include <cuda_runtime.h>
#include <cstdint>

#define NN 50000
#define D  128
#define DO 64
#define CAP 128

__device__ float g_xr  [NN * D];   // x pre-rounded to tf32 bit patterns
__device__ float g_agg [NN * D];   // layer-1 neighbor mean (tf32-rounded)
__device__ float g_h   [NN * D];   // relu(layer-1 out) (tf32-rounded)
__device__ float g_hl  [NN * DO];  // h @ W2_l (full fp32)
__device__ float g_base[NN * DO];  // h @ W2_r + b2 (full fp32)
__device__ int   g_cnt [NN];
__device__ int   g_csr [NN * CAP];
__device__ int   g_idx64;

// ---------------------------------------------------------------------------
__global__ void detect_kernel(const int* __restrict__ ei, int E) {
    int n = E < 512 ? E : 512;
    int i = threadIdx.x;
    int nz = (i < n && ei[2 * i + 1] != 0) ? 1 : 0;
    int any = __syncthreads_or(nz);
    if (i == 0) g_idx64 = any ? 0 : 1;
}

__device__ __forceinline__ int load_idx(const void* ei, long long pos) {
    if (g_idx64) return (int)((const long long*)ei)[pos];
    return ((const int*)ei)[pos];
}

__global__ void fill_kernel(const void* __restrict__ ei, int E) {
    int e = blockIdx.x * blockDim.x + threadIdx.x;
    if (e >= E) return;
    int src = load_idx(ei, e);
    int dst = load_idx(ei, (long long)E + e);
    int pos = atomicAdd(&g_cnt[dst], 1);
    if (pos < CAP) g_csr[dst * CAP + pos] = src;
}

// ---------------------------------------------------------------------------
// tf32 helpers
// ---------------------------------------------------------------------------
__device__ __forceinline__ uint32_t f2tf32(float f) {
    uint32_t r;
    asm("cvt.rna.tf32.f32 %0, %1;" : "=r"(r) : "f"(f));
    return r;
}

__device__ __forceinline__ void mma_tf32(float& d0, float& d1, float& d2, float& d3,
                                         uint32_t a0, uint32_t a1, uint32_t a2, uint32_t a3,
                                         uint32_t b0, uint32_t b1) {
    asm volatile(
        "mma.sync.aligned.m16n8k8.row.col.f32.tf32.tf32.f32 "
        "{%0,%1,%2,%3}, {%4,%5,%6,%7}, {%8,%9}, {%0,%1,%2,%3};"
        : "+f"(d0), "+f"(d1), "+f"(d2), "+f"(d3)
        : "r"(a0), "r"(a1), "r"(a2), "r"(a3), "r"(b0), "r"(b1));
}

__device__ __forceinline__ void cpasync16(uint32_t saddr, const void* g) {
    asm volatile("cp.async.cg.shared.global [%0], [%1], 16;"
                 :: "r"(saddr), "l"(g) : "memory");
}
#define CP_COMMIT() asm volatile("cp.async.commit_group;" ::: "memory")

// k-permutation within each 8-group: fragment pair (k, k+4) -> adjacent
__device__ __forceinline__ int kperm(int k) {
    return (k & ~7) + 2 * (k & 3) + ((k >> 2) & 1);
}

// ---------------------------------------------------------------------------
// Pre-round x to tf32 bit patterns (enables raw cp.async streaming in gemm1)
// ---------------------------------------------------------------------------
__global__ void roundx_kernel(const float* __restrict__ x) {
    int i = blockIdx.x * blockDim.x + threadIdx.x;  // over NN*D/4
    if (i >= NN * D / 4) return;
    float4 v = ((const float4*)x)[i];
    ((uint4*)g_xr)[i] = make_uint4(f2tf32(v.x), f2tf32(v.y),
                                   f2tf32(v.z), f2tf32(v.w));
}

// ---------------------------------------------------------------------------
// Aggregation 1: warp per dst node; mean of x rows -> g_agg (tf32-rounded)
// ---------------------------------------------------------------------------
__global__ void agg1_kernel() {
    int t = blockIdx.x * blockDim.x + threadIdx.x;
    int node = t >> 5;
    if (node >= NN) return;
    int lane = t & 31;
    int deg = g_cnt[node];
    int degc = deg < CAP ? deg : CAP;
    const int* nb = g_csr + (size_t)node * CAP;
    float4 acc = make_float4(0.f, 0.f, 0.f, 0.f);
    for (int i = 0; i < degc; i++) {
        int src = nb[i];
        float4 v = *(const float4*)(g_xr + (size_t)src * D + lane * 4);
        acc.x += v.x; acc.y += v.y; acc.z += v.z; acc.w += v.w;
    }
    float inv = 1.0f / (float)(deg > 0 ? deg : 1);
    *(uint4*)(g_agg + (size_t)node * D + lane * 4) =
        make_uint4(f2tf32(acc.x * inv), f2tf32(acc.y * inv),
                   f2tf32(acc.z * inv), f2tf32(acc.w * inv));
}

#define SA_STR 36
#define NTILES ((NN + 127) / 128)

// ---------------------------------------------------------------------------
// GEMM1: h = relu([agg | xr] @ [W1l ; W1r] + b1)   (M=NN, K=256, N=128)
// Grid NTILES*2 (tile 128x64). sW n-major [64][264] k-permuted; double-
// buffered sA [2][128][36] filled by cp.async (A is pre-rounded tf32).
// smem = 67.6K + 36.9K = 104.4KB -> 2 CTAs/SM. Warp tile 32x32.
// ---------------------------------------------------------------------------
#define G1_SWK 264
#define G1_SMEM ((64 * G1_SWK + 2 * 128 * SA_STR) * 4)

__global__ void __launch_bounds__(256, 2)
gemm1_kernel(const float* __restrict__ W1l,
             const float* __restrict__ b1,
             const float* __restrict__ W1r) {
    extern __shared__ uint32_t smu[];
    uint32_t* sW = smu;
    uint32_t* sA = smu + 64 * G1_SWK;
    const uint32_t sAaddr = (uint32_t)__cvta_generic_to_shared(sA);

    const int tid  = threadIdx.x;
    const int wid  = tid >> 5;
    const int lane = tid & 31;
    const int gid  = lane >> 2;
    const int tig  = lane & 3;
    const int wm   = wid & 3;
    const int wn   = wid >> 2;
    const int tile = blockIdx.x >> 1;
    const int half = blockIdx.x & 1;
    const int tile_row = tile * 128;

    // stage chunk c (32 k-cols of [agg|xr]) into buffer buf via cp.async
    auto stage = [&](int c, int buf) {
        uint32_t base = sAaddr + (uint32_t)buf * (128 * SA_STR * 4);
#pragma unroll
        for (int i = tid; i < 1024; i += 256) {
            int r = i >> 3, j = i & 7;
            int row = tile_row + r;
            uint32_t daddr = base + (uint32_t)(r * SA_STR + j * 4) * 4;
            if (row < NN) {
                const float* src = (c < 4)
                    ? (g_agg + (size_t)row * D + c * 32 + j * 4)
                    : (g_xr + (size_t)row * D + (c - 4) * 32 + j * 4);
                cpasync16(daddr, src);
            } else {
                asm volatile("st.shared.v4.b32 [%0], {%1,%1,%1,%1};"
                             :: "r"(daddr), "r"(0) : "memory");
            }
        }
        CP_COMMIT();
    };

    stage(0, 0);

    // weights: n-major, k-permuted (overlaps with chunk-0 cp.async)
    for (int i = tid; i < 64 * 256; i += 256) {
        int k = i >> 6, n = i & 63;
        int ng = half * 64 + n;
        float w = (k < 128) ? W1l[k * 128 + ng] : W1r[(k - 128) * 128 + ng];
        sW[n * G1_SWK + kperm(k)] = f2tf32(w);
    }

    float acc[2][4][4];
#pragma unroll
    for (int mt = 0; mt < 2; mt++)
#pragma unroll
        for (int nt = 0; nt < 4; nt++)
#pragma unroll
            for (int q = 0; q < 4; q++) acc[mt][nt][q] = 0.f;

    for (int c = 0; c < 8; c++) {
        if (c + 1 < 8) stage(c + 1, (c + 1) & 1);
        if (c + 1 < 8) { asm volatile("cp.async.wait_group 1;" ::: "memory"); }
        else           { asm volatile("cp.async.wait_group 0;" ::: "memory"); }
        __syncthreads();

        const uint32_t* sAb = sA + (c & 1) * (128 * SA_STR);
#pragma unroll
        for (int ks = 0; ks < 4; ks++) {
            int kk = ks * 8;
            int kg = c * 32 + kk;
            uint2 b[4];
#pragma unroll
            for (int nt = 0; nt < 4; nt++) {
                int n0 = wn * 32 + nt * 8 + gid;
                b[nt] = *(const uint2*)(sW + n0 * G1_SWK + kg + 2 * tig);
            }
            uint32_t a[2][4];
#pragma unroll
            for (int mt = 0; mt < 2; mt++) {
                int m0 = wm * 32 + mt * 16;
                a[mt][0] = sAb[(m0 + gid) * SA_STR + kk + tig];
                a[mt][1] = sAb[(m0 + gid + 8) * SA_STR + kk + tig];
                a[mt][2] = sAb[(m0 + gid) * SA_STR + kk + tig + 4];
                a[mt][3] = sAb[(m0 + gid + 8) * SA_STR + kk + tig + 4];
            }
#pragma unroll
            for (int mt = 0; mt < 2; mt++)
#pragma unroll
                for (int nt = 0; nt < 4; nt++)
                    mma_tf32(acc[mt][nt][0], acc[mt][nt][1],
                             acc[mt][nt][2], acc[mt][nt][3],
                             a[mt][0], a[mt][1], a[mt][2], a[mt][3],
                             b[nt].x, b[nt].y);
        }
        __syncthreads();
    }

    // epilogue: + b1, relu, round to tf32, store g_h
#pragma unroll
    for (int mt = 0; mt < 2; mt++) {
#pragma unroll
        for (int nt = 0; nt < 4; nt++) {
            int n0 = half * 64 + wn * 32 + nt * 8 + 2 * tig;
            float bb0 = b1[n0], bb1 = b1[n0 + 1];
            int r0 = tile_row + wm * 32 + mt * 16 + gid;
            if (r0 < NN)
                *(uint2*)(g_h + (size_t)r0 * D + n0) =
                    make_uint2(f2tf32(fmaxf(acc[mt][nt][0] + bb0, 0.f)),
                               f2tf32(fmaxf(acc[mt][nt][1] + bb1, 0.f)));
            if (r0 + 8 < NN)
                *(uint2*)(g_h + (size_t)(r0 + 8) * D + n0) =
                    make_uint2(f2tf32(fmaxf(acc[mt][nt][2] + bb0, 0.f)),
                               f2tf32(fmaxf(acc[mt][nt][3] + bb1, 0.f)));
        }
    }
}

// ---------------------------------------------------------------------------
// GEMM2: half 0: hl = h @ W2l ; half 1: base = h @ W2r + b2
// sW [64][136] + 2x sA -> 71.6KB smem -> 3 CTAs/SM.
// ---------------------------------------------------------------------------
#define G2_SWK 136
#define G2_SMEM ((64 * G2_SWK + 2 * 128 * SA_STR) * 4)

__global__ void __launch_bounds__(256, 3)
gemm2_kernel(const float* __restrict__ W2l,
             const float* __restrict__ b2,
             const float* __restrict__ W2r) {
    extern __shared__ uint32_t smu[];
    uint32_t* sW = smu;
    uint32_t* sA = smu + 64 * G2_SWK;
    const uint32_t sAaddr = (uint32_t)__cvta_generic_to_shared(sA);

    const int tid  = threadIdx.x;
    const int wid  = tid >> 5;
    const int lane = tid & 31;
    const int gid  = lane >> 2;
    const int tig  = lane & 3;
    const int wm   = wid & 3;
    const int wn   = wid >> 2;
    const int tile = blockIdx.x >> 1;
    const int half = blockIdx.x & 1;
    const int tile_row = tile * 128;

    auto stage = [&](int c, int buf) {
        uint32_t base = sAaddr + (uint32_t)buf * (128 * SA_STR * 4);
#pragma unroll
        for (int i = tid; i < 1024; i += 256) {
            int r = i >> 3, j = i & 7;
            int row = tile_row + r;
            uint32_t daddr = base + (uint32_t)(r * SA_STR + j * 4) * 4;
            if (row < NN)
                cpasync16(daddr, g_h + (size_t)row * D + c * 32 + j * 4);
            else
                asm volatile("st.shared.v4.b32 [%0], {%1,%1,%1,%1};"
                             :: "r"(daddr), "r"(0) : "memory");
        }
        CP_COMMIT();
    };

    stage(0, 0);

    const float* W = half ? W2r : W2l;
    for (int i = tid; i < 64 * 128; i += 256) {
        int k = i >> 6, n = i & 63;
        sW[n * G2_SWK + kperm(k)] = f2tf32(W[k * 64 + n]);
    }

    float acc[2][4][4];
#pragma unroll
    for (int mt = 0; mt < 2; mt++)
#pragma unroll
        for (int nt = 0; nt < 4; nt++)
#pragma unroll
            for (int q = 0; q < 4; q++) acc[mt][nt][q] = 0.f;

    for (int c = 0; c < 4; c++) {
        if (c + 1 < 4) stage(c + 1, (c + 1) & 1);
        if (c + 1 < 4) { asm volatile("cp.async.wait_group 1;" ::: "memory"); }
        else           { asm volatile("cp.async.wait_group 0;" ::: "memory"); }
        __syncthreads();

        const uint32_t* sAb = sA + (c & 1) * (128 * SA_STR);
#pragma unroll
        for (int ks = 0; ks < 4; ks++) {
            int kk = ks * 8;
            int kg = c * 32 + kk;
            uint2 b[4];
#pragma unroll
            for (int nt = 0; nt < 4; nt++) {
                int n0 = wn * 32 + nt * 8 + gid;
                b[nt] = *(const uint2*)(sW + n0 * G2_SWK + kg + 2 * tig);
            }
            uint32_t a[2][4];
#pragma unroll
            for (int mt = 0; mt < 2; mt++) {
                int m0 = wm * 32 + mt * 16;
                a[mt][0] = sAb[(m0 + gid) * SA_STR + kk + tig];
                a[mt][1] = sAb[(m0 + gid + 8) * SA_STR + kk + tig];
                a[mt][2] = sAb[(m0 + gid) * SA_STR + kk + tig + 4];
                a[mt][3] = sAb[(m0 + gid + 8) * SA_STR + kk + tig + 4];
            }
#pragma unroll
            for (int mt = 0; mt < 2; mt++)
#pragma unroll
                for (int nt = 0; nt < 4; nt++)
                    mma_tf32(acc[mt][nt][0], acc[mt][nt][1],
                             acc[mt][nt][2], acc[mt][nt][3],
                             a[mt][0], a[mt][1], a[mt][2], a[mt][3],
                             b[nt].x, b[nt].y);
        }
        __syncthreads();
    }

#pragma unroll
    for (int mt = 0; mt < 2; mt++) {
#pragma unroll
        for (int nt = 0; nt < 4; nt++) {
            int n0 = wn * 32 + nt * 8 + 2 * tig;
            int r0 = tile_row + wm * 32 + mt * 16 + gid;
            if (half == 0) {
                if (r0 < NN)
                    *(float2*)(g_hl + (size_t)r0 * DO + n0) =
                        make_float2(acc[mt][nt][0], acc[mt][nt][1]);
                if (r0 + 8 < NN)
                    *(float2*)(g_hl + (size_t)(r0 + 8) * DO + n0) =
                        make_float2(acc[mt][nt][2], acc[mt][nt][3]);
            } else {
                float bb0 = b2[n0], bb1 = b2[n0 + 1];
                if (r0 < NN)
                    *(float2*)(g_base + (size_t)r0 * DO + n0) =
                        make_float2(acc[mt][nt][0] + bb0, acc[mt][nt][1] + bb1);
                if (r0 + 8 < NN)
                    *(float2*)(g_base + (size_t)(r0 + 8) * DO + n0) =
                        make_float2(acc[mt][nt][2] + bb0, acc[mt][nt][3] + bb1);
            }
        }
    }
}

// ---------------------------------------------------------------------------
// Aggregation 2 + finish: out = mean_j(g_hl[src_j]) + g_base
// ---------------------------------------------------------------------------
__global__ void agg2_kernel(float* __restrict__ out) {
    int t = blockIdx.x * blockDim.x + threadIdx.x;
    int node = t >> 5;
    if (node >= NN) return;
    int lane = t & 31;
    int deg = g_cnt[node];
    int degc = deg < CAP ? deg : CAP;
    const int* nb = g_csr + (size_t)node * CAP;
    float2 acc = make_float2(0.f, 0.f);
    for (int i = 0; i < degc; i++) {
        int src = nb[i];
        float2 v = *(const float2*)(g_hl + (size_t)src * DO + lane * 2);
        acc.x += v.x; acc.y += v.y;
    }
    float inv = 1.0f / (float)(deg > 0 ? deg : 1);
    float2 b = *(const float2*)(g_base + (size_t)node * DO + lane * 2);
    *(float2*)(out + (size_t)node * DO + lane * 2) =
        make_float2(acc.x * inv + b.x, acc.y * inv + b.y);
}

extern "C" void kernel_launch(void* const* d_in, const int* in_sizes, int n_in,
                              void* d_out, int out_size) {
    const float* x   = (const float*)d_in[0];
    const void*  ei  = d_in[1];
    const float* W1l = (const float*)d_in[2];
    const float* b1  = (const float*)d_in[3];
    const float* W1r = (const float*)d_in[4];
    const float* W2l = (const float*)d_in[5];
    const float* b2  = (const float*)d_in[6];
    const float* W2r = (const float*)d_in[7];
    float* out = (float*)d_out;

    int E = in_sizes[1] / 2;

    void* p_cnt;
    cudaGetSymbolAddress(&p_cnt, g_cnt);

    cudaFuncSetAttribute(gemm1_kernel,
                         cudaFuncAttributeMaxDynamicSharedMemorySize, G1_SMEM);
    cudaFuncSetAttribute(gemm2_kernel,
                         cudaFuncAttributeMaxDynamicSharedMemorySize, G2_SMEM);

    cudaMemsetAsync(p_cnt, 0, (size_t)NN * sizeof(int));

    detect_kernel<<<1, 512>>>((const int*)ei, E);
    roundx_kernel<<<(NN * D / 4 + 255) / 256, 256>>>(x);
    fill_kernel<<<(E + 255) / 256, 256>>>(ei, E);

    agg1_kernel<<<(NN * 32 + 255) / 256, 256>>>();

    gemm1_kernel<<<NTILES * 2, 256, G1_SMEM>>>(W1l, b1, W1r);
    gemm2_kernel<<<NTILES * 2, 256, G2_SMEM>>>(W2l, b2, W2r);

    agg2_kernel<<<(NN * 32 + 255) / 256, 256>>>(out);
}

// round 10
// speedup vs baseline: 1.0644x; 1.0644x over previous
#include <cuda_runtime.h>
#include <cstdint>

#define NN 50000
#define D  128
#define DO 64
#define CAP 128

__device__ float g_xr  [NN * D];    // x pre-rounded to tf32 bit patterns
__device__ float g_agg [NN * D];    // layer-1 neighbor mean (tf32-rounded)
__device__ float g_h   [NN * D];    // relu(layer-1 out) (tf32-rounded)
__device__ float g_hl  [NN * DO];   // h @ W2_l
__device__ float g_base[NN * DO];   // h @ W2_r + b2
__device__ int   g_cnt [NN];
__device__ int   g_csr [NN * CAP];
__device__ int   g_idx64;

#define G1_SWK 264
#define G2_SWK 136
__device__ float g_w1t[2][64 * G1_SWK];  // W1 n-major, k-permuted, tf32 bits
__device__ float g_w2t[2][64 * G2_SWK];  // W2 (l|r) n-major, k-permuted

// ---------------------------------------------------------------------------
__global__ void detect_kernel(const int* __restrict__ ei, int E) {
    int n = E < 512 ? E : 512;
    int i = threadIdx.x;
    int nz = (i < n && ei[2 * i + 1] != 0) ? 1 : 0;
    int any = __syncthreads_or(nz);
    if (i == 0) g_idx64 = any ? 0 : 1;
}

__device__ __forceinline__ int load_idx(const void* ei, long long pos) {
    if (g_idx64) return (int)((const long long*)ei)[pos];
    return ((const int*)ei)[pos];
}

__global__ void fill_kernel(const void* __restrict__ ei, int E) {
    int half = (E + 1) >> 1;
    int e = blockIdx.x * blockDim.x + threadIdx.x;
    if (e >= half) return;
    int src0 = load_idx(ei, e);
    int dst0 = load_idx(ei, (long long)E + e);
    int e2 = e + half;
    if (e2 < E) {
        int src1 = load_idx(ei, e2);
        int dst1 = load_idx(ei, (long long)E + e2);
        int p0 = atomicAdd(&g_cnt[dst0], 1);
        int p1 = atomicAdd(&g_cnt[dst1], 1);
        if (p0 < CAP) g_csr[dst0 * CAP + p0] = src0;
        if (p1 < CAP) g_csr[dst1 * CAP + p1] = src1;
    } else {
        int p0 = atomicAdd(&g_cnt[dst0], 1);
        if (p0 < CAP) g_csr[dst0 * CAP + p0] = src0;
    }
}

// ---------------------------------------------------------------------------
// tf32 helpers
// ---------------------------------------------------------------------------
__device__ __forceinline__ uint32_t f2tf32(float f) {
    uint32_t r;
    asm("cvt.rna.tf32.f32 %0, %1;" : "=r"(r) : "f"(f));
    return r;
}

__device__ __forceinline__ void mma_tf32(float& d0, float& d1, float& d2, float& d3,
                                         uint32_t a0, uint32_t a1, uint32_t a2, uint32_t a3,
                                         uint32_t b0, uint32_t b1) {
    asm volatile(
        "mma.sync.aligned.m16n8k8.row.col.f32.tf32.tf32.f32 "
        "{%0,%1,%2,%3}, {%4,%5,%6,%7}, {%8,%9}, {%0,%1,%2,%3};"
        : "+f"(d0), "+f"(d1), "+f"(d2), "+f"(d3)
        : "r"(a0), "r"(a1), "r"(a2), "r"(a3), "r"(b0), "r"(b1));
}

__device__ __forceinline__ void cpasync16(uint32_t saddr, const void* g) {
    asm volatile("cp.async.cg.shared.global [%0], [%1], 16;"
                 :: "r"(saddr), "l"(g) : "memory");
}
#define CP_COMMIT() asm volatile("cp.async.commit_group;" ::: "memory")

__device__ __forceinline__ int kperm(int k) {
    return (k & ~7) + 2 * (k & 3) + ((k >> 2) & 1);
}

// ---------------------------------------------------------------------------
// Pre-round x; pre-transform weights (n-major, k-permuted, tf32)
// ---------------------------------------------------------------------------
__global__ void roundx_kernel(const float* __restrict__ x) {
    int i = blockIdx.x * blockDim.x + threadIdx.x;
    if (i >= NN * D / 4) return;
    float4 v = ((const float4*)x)[i];
    ((uint4*)g_xr)[i] = make_uint4(f2tf32(v.x), f2tf32(v.y),
                                   f2tf32(v.z), f2tf32(v.w));
}

__global__ void prepw_kernel(const float* __restrict__ W1l,
                             const float* __restrict__ W1r,
                             const float* __restrict__ W2l,
                             const float* __restrict__ W2r) {
    int i = blockIdx.x * blockDim.x + threadIdx.x;
    if (i < 256 * 128) {
        int k = i >> 7, n = i & 127;
        float w = (k < 128) ? W1l[k * 128 + n] : W1r[(k - 128) * 128 + n];
        int h = n >> 6, nl = n & 63;
        ((uint32_t*)g_w1t[h])[nl * G1_SWK + kperm(k)] = f2tf32(w);
    } else if (i < 256 * 128 + 128 * 128) {
        int j = i - 256 * 128;
        int k = j >> 7, n = j & 127;
        int h = n >> 6, nl = n & 63;
        const float* W = h ? W2r : W2l;
        ((uint32_t*)g_w2t[h])[nl * G2_SWK + kperm(k)] = f2tf32(W[k * 64 + nl]);
    }
}

// ---------------------------------------------------------------------------
// Aggregation 1: warp per dst node; mean of xr rows -> g_agg (unroll x4, MLP)
// ---------------------------------------------------------------------------
__global__ void agg1_kernel() {
    int t = blockIdx.x * blockDim.x + threadIdx.x;
    int node = t >> 5;
    if (node >= NN) return;
    int lane = t & 31;
    int deg = g_cnt[node];
    int degc = deg < CAP ? deg : CAP;
    const int* nb = g_csr + (size_t)node * CAP;
    float4 a0 = make_float4(0,0,0,0), a1 = a0, a2 = a0, a3 = a0;
    int i = 0;
    for (; i + 4 <= degc; i += 4) {
        int4 s = *(const int4*)(nb + i);
        float4 v0 = *(const float4*)(g_xr + (size_t)s.x * D + lane * 4);
        float4 v1 = *(const float4*)(g_xr + (size_t)s.y * D + lane * 4);
        float4 v2 = *(const float4*)(g_xr + (size_t)s.z * D + lane * 4);
        float4 v3 = *(const float4*)(g_xr + (size_t)s.w * D + lane * 4);
        a0.x += v0.x; a0.y += v0.y; a0.z += v0.z; a0.w += v0.w;
        a1.x += v1.x; a1.y += v1.y; a1.z += v1.z; a1.w += v1.w;
        a2.x += v2.x; a2.y += v2.y; a2.z += v2.z; a2.w += v2.w;
        a3.x += v3.x; a3.y += v3.y; a3.z += v3.z; a3.w += v3.w;
    }
    for (; i < degc; i++) {
        float4 v = *(const float4*)(g_xr + (size_t)nb[i] * D + lane * 4);
        a0.x += v.x; a0.y += v.y; a0.z += v.z; a0.w += v.w;
    }
    float4 s;
    s.x = (a0.x + a1.x) + (a2.x + a3.x);
    s.y = (a0.y + a1.y) + (a2.y + a3.y);
    s.z = (a0.z + a1.z) + (a2.z + a3.z);
    s.w = (a0.w + a1.w) + (a2.w + a3.w);
    float inv = 1.0f / (float)(deg > 0 ? deg : 1);
    *(uint4*)(g_agg + (size_t)node * D + lane * 4) =
        make_uint4(f2tf32(s.x * inv), f2tf32(s.y * inv),
                   f2tf32(s.z * inv), f2tf32(s.w * inv));
}

#define SA_STR 36
#define NTILES ((NN + 127) / 128)

// ---------------------------------------------------------------------------
// GEMM1: h = relu([agg | xr] @ W1t + b1)  (tile 128 rows x 64 cols)
// Weights cp.async'd from pre-transformed g_w1t (no cvt, no conflicts).
// ---------------------------------------------------------------------------
#define G1_SMEM ((64 * G1_SWK + 2 * 128 * SA_STR) * 4)

__global__ void __launch_bounds__(256, 2)
gemm1_kernel(const float* __restrict__ b1) {
    extern __shared__ uint32_t smu[];
    uint32_t* sW = smu;
    uint32_t* sA = smu + 64 * G1_SWK;
    const uint32_t sWaddr = (uint32_t)__cvta_generic_to_shared(sW);
    const uint32_t sAaddr = (uint32_t)__cvta_generic_to_shared(sA);

    const int tid  = threadIdx.x;
    const int wid  = tid >> 5;
    const int lane = tid & 31;
    const int gid  = lane >> 2;
    const int tig  = lane & 3;
    const int wm   = wid & 3;
    const int wn   = wid >> 2;
    const int tile = blockIdx.x >> 1;
    const int half = blockIdx.x & 1;
    const int tile_row = tile * 128;

    auto stage = [&](int c, int buf) {
        uint32_t base = sAaddr + (uint32_t)buf * (128 * SA_STR * 4);
#pragma unroll
        for (int i = tid; i < 1024; i += 256) {
            int r = i >> 3, j = i & 7;
            int row = tile_row + r;
            uint32_t daddr = base + (uint32_t)(r * SA_STR + j * 4) * 4;
            if (row < NN) {
                const float* src = (c < 4)
                    ? (g_agg + (size_t)row * D + c * 32 + j * 4)
                    : (g_xr + (size_t)row * D + (c - 4) * 32 + j * 4);
                cpasync16(daddr, src);
            } else {
                asm volatile("st.shared.v4.b32 [%0], {%1,%1,%1,%1};"
                             :: "r"(daddr), "r"(0) : "memory");
            }
        }
        CP_COMMIT();
    };

    stage(0, 0);  // group 0

    // weights: raw cp.async of pre-transformed panel (group 1)
    {
        const float* wsrc = g_w1t[half];
        for (int i = tid * 4; i < 64 * G1_SWK; i += 1024)
            cpasync16(sWaddr + (uint32_t)i * 4, wsrc + i);
        CP_COMMIT();
    }

    float acc[2][4][4];
#pragma unroll
    for (int mt = 0; mt < 2; mt++)
#pragma unroll
        for (int nt = 0; nt < 4; nt++)
#pragma unroll
            for (int q = 0; q < 4; q++) acc[mt][nt][q] = 0.f;

    for (int c = 0; c < 8; c++) {
        if (c + 1 < 8) {
            stage(c + 1, (c + 1) & 1);
            asm volatile("cp.async.wait_group 1;" ::: "memory");
        } else {
            asm volatile("cp.async.wait_group 0;" ::: "memory");
        }
        __syncthreads();

        const uint32_t* sAb = sA + (c & 1) * (128 * SA_STR);
#pragma unroll
        for (int ks = 0; ks < 4; ks++) {
            int kk = ks * 8;
            int kg = c * 32 + kk;
            uint2 b[4];
#pragma unroll
            for (int nt = 0; nt < 4; nt++) {
                int n0 = wn * 32 + nt * 8 + gid;
                b[nt] = *(const uint2*)(sW + n0 * G1_SWK + kg + 2 * tig);
            }
            uint32_t a[2][4];
#pragma unroll
            for (int mt = 0; mt < 2; mt++) {
                int m0 = wm * 32 + mt * 16;
                a[mt][0] = sAb[(m0 + gid) * SA_STR + kk + tig];
                a[mt][1] = sAb[(m0 + gid + 8) * SA_STR + kk + tig];
                a[mt][2] = sAb[(m0 + gid) * SA_STR + kk + tig + 4];
                a[mt][3] = sAb[(m0 + gid + 8) * SA_STR + kk + tig + 4];
            }
#pragma unroll
            for (int mt = 0; mt < 2; mt++)
#pragma unroll
                for (int nt = 0; nt < 4; nt++)
                    mma_tf32(acc[mt][nt][0], acc[mt][nt][1],
                             acc[mt][nt][2], acc[mt][nt][3],
                             a[mt][0], a[mt][1], a[mt][2], a[mt][3],
                             b[nt].x, b[nt].y);
        }
        __syncthreads();
    }

#pragma unroll
    for (int mt = 0; mt < 2; mt++) {
#pragma unroll
        for (int nt = 0; nt < 4; nt++) {
            int n0 = half * 64 + wn * 32 + nt * 8 + 2 * tig;
            float bb0 = b1[n0], bb1 = b1[n0 + 1];
            int r0 = tile_row + wm * 32 + mt * 16 + gid;
            if (r0 < NN)
                *(uint2*)(g_h + (size_t)r0 * D + n0) =
                    make_uint2(f2tf32(fmaxf(acc[mt][nt][0] + bb0, 0.f)),
                               f2tf32(fmaxf(acc[mt][nt][1] + bb1, 0.f)));
            if (r0 + 8 < NN)
                *(uint2*)(g_h + (size_t)(r0 + 8) * D + n0) =
                    make_uint2(f2tf32(fmaxf(acc[mt][nt][2] + bb0, 0.f)),
                               f2tf32(fmaxf(acc[mt][nt][3] + bb1, 0.f)));
        }
    }
}

// ---------------------------------------------------------------------------
// GEMM2: half 0: hl = h @ W2l ; half 1: base = h @ W2r + b2
// ---------------------------------------------------------------------------
#define G2_SMEM ((64 * G2_SWK + 2 * 128 * SA_STR) * 4)

__global__ void __launch_bounds__(256, 3)
gemm2_kernel(const float* __restrict__ b2) {
    extern __shared__ uint32_t smu[];
    uint32_t* sW = smu;
    uint32_t* sA = smu + 64 * G2_SWK;
    const uint32_t sWaddr = (uint32_t)__cvta_generic_to_shared(sW);
    const uint32_t sAaddr = (uint32_t)__cvta_generic_to_shared(sA);

    const int tid  = threadIdx.x;
    const int wid  = tid >> 5;
    const int lane = tid & 31;
    const int gid  = lane >> 2;
    const int tig  = lane & 3;
    const int wm   = wid & 3;
    const int wn   = wid >> 2;
    const int tile = blockIdx.x >> 1;
    const int half = blockIdx.x & 1;
    const int tile_row = tile * 128;

    auto stage = [&](int c, int buf) {
        uint32_t base = sAaddr + (uint32_t)buf * (128 * SA_STR * 4);
#pragma unroll
        for (int i = tid; i < 1024; i += 256) {
            int r = i >> 3, j = i & 7;
            int row = tile_row + r;
            uint32_t daddr = base + (uint32_t)(r * SA_STR + j * 4) * 4;
            if (row < NN)
                cpasync16(daddr, g_h + (size_t)row * D + c * 32 + j * 4);
            else
                asm volatile("st.shared.v4.b32 [%0], {%1,%1,%1,%1};"
                             :: "r"(daddr), "r"(0) : "memory");
        }
        CP_COMMIT();
    };

    stage(0, 0);
    {
        const float* wsrc = g_w2t[half];
        for (int i = tid * 4; i < 64 * G2_SWK; i += 1024)
            cpasync16(sWaddr + (uint32_t)i * 4, wsrc + i);
        CP_COMMIT();
    }

    float acc[2][4][4];
#pragma unroll
    for (int mt = 0; mt < 2; mt++)
#pragma unroll
        for (int nt = 0; nt < 4; nt++)
#pragma unroll
            for (int q = 0; q < 4; q++) acc[mt][nt][q] = 0.f;

    for (int c = 0; c < 4; c++) {
        if (c + 1 < 4) {
            stage(c + 1, (c + 1) & 1);
            asm volatile("cp.async.wait_group 1;" ::: "memory");
        } else {
            asm volatile("cp.async.wait_group 0;" ::: "memory");
        }
        __syncthreads();

        const uint32_t* sAb = sA + (c & 1) * (128 * SA_STR);
#pragma unroll
        for (int ks = 0; ks < 4; ks++) {
            int kk = ks * 8;
            int kg = c * 32 + kk;
            uint2 b[4];
#pragma unroll
            for (int nt = 0; nt < 4; nt++) {
                int n0 = wn * 32 + nt * 8 + gid;
                b[nt] = *(const uint2*)(sW + n0 * G2_SWK + kg + 2 * tig);
            }
            uint32_t a[2][4];
#pragma unroll
            for (int mt = 0; mt < 2; mt++) {
                int m0 = wm * 32 + mt * 16;
                a[mt][0] = sAb[(m0 + gid) * SA_STR + kk + tig];
                a[mt][1] = sAb[(m0 + gid + 8) * SA_STR + kk + tig];
                a[mt][2] = sAb[(m0 + gid) * SA_STR + kk + tig + 4];
                a[mt][3] = sAb[(m0 + gid + 8) * SA_STR + kk + tig + 4];
            }
#pragma unroll
            for (int mt = 0; mt < 2; mt++)
#pragma unroll
                for (int nt = 0; nt < 4; nt++)
                    mma_tf32(acc[mt][nt][0], acc[mt][nt][1],
                             acc[mt][nt][2], acc[mt][nt][3],
                             a[mt][0], a[mt][1], a[mt][2], a[mt][3],
                             b[nt].x, b[nt].y);
        }
        __syncthreads();
    }

#pragma unroll
    for (int mt = 0; mt < 2; mt++) {
#pragma unroll
        for (int nt = 0; nt < 4; nt++) {
            int n0 = wn * 32 + nt * 8 + 2 * tig;
            int r0 = tile_row + wm * 32 + mt * 16 + gid;
            if (half == 0) {
                if (r0 < NN)
                    *(float2*)(g_hl + (size_t)r0 * DO + n0) =
                        make_float2(acc[mt][nt][0], acc[mt][nt][1]);
                if (r0 + 8 < NN)
                    *(float2*)(g_hl + (size_t)(r0 + 8) * DO + n0) =
                        make_float2(acc[mt][nt][2], acc[mt][nt][3]);
            } else {
                float bb0 = b2[n0], bb1 = b2[n0 + 1];
                if (r0 < NN)
                    *(float2*)(g_base + (size_t)r0 * DO + n0) =
                        make_float2(acc[mt][nt][0] + bb0, acc[mt][nt][1] + bb1);
                if (r0 + 8 < NN)
                    *(float2*)(g_base + (size_t)(r0 + 8) * DO + n0) =
                        make_float2(acc[mt][nt][2] + bb0, acc[mt][nt][3] + bb1);
            }
        }
    }
}

// ---------------------------------------------------------------------------
// Aggregation 2 + finish: out = mean_j(g_hl[src_j]) + g_base (unroll x4)
// ---------------------------------------------------------------------------
__global__ void agg2_kernel(float* __restrict__ out) {
    int t = blockIdx.x * blockDim.x + threadIdx.x;
    int node = t >> 5;
    if (node >= NN) return;
    int lane = t & 31;
    int deg = g_cnt[node];
    int degc = deg < CAP ? deg : CAP;
    const int* nb = g_csr + (size_t)node * CAP;
    float2 a0 = make_float2(0,0), a1 = a0, a2 = a0, a3 = a0;
    int i = 0;
    for (; i + 4 <= degc; i += 4) {
        int4 s = *(const int4*)(nb + i);
        float2 v0 = *(const float2*)(g_hl + (size_t)s.x * DO + lane * 2);
        float2 v1 = *(const float2*)(g_hl + (size_t)s.y * DO + lane * 2);
        float2 v2 = *(const float2*)(g_hl + (size_t)s.z * DO + lane * 2);
        float2 v3 = *(const float2*)(g_hl + (size_t)s.w * DO + lane * 2);
        a0.x += v0.x; a0.y += v0.y;
        a1.x += v1.x; a1.y += v1.y;
        a2.x += v2.x; a2.y += v2.y;
        a3.x += v3.x; a3.y += v3.y;
    }
    for (; i < degc; i++) {
        float2 v = *(const float2*)(g_hl + (size_t)nb[i] * DO + lane * 2);
        a0.x += v.x; a0.y += v.y;
    }
    float2 s = make_float2((a0.x + a1.x) + (a2.x + a3.x),
                           (a0.y + a1.y) + (a2.y + a3.y));
    float inv = 1.0f / (float)(deg > 0 ? deg : 1);
    float2 b = *(const float2*)(g_base + (size_t)node * DO + lane * 2);
    *(float2*)(out + (size_t)node * DO + lane * 2) =
        make_float2(s.x * inv + b.x, s.y * inv + b.y);
}

extern "C" void kernel_launch(void* const* d_in, const int* in_sizes, int n_in,
                              void* d_out, int out_size) {
    const float* x   = (const float*)d_in[0];
    const void*  ei  = d_in[1];
    const float* W1l = (const float*)d_in[2];
    const float* b1  = (const float*)d_in[3];
    const float* W1r = (const float*)d_in[4];
    const float* W2l = (const float*)d_in[5];
    const float* b2  = (const float*)d_in[6];
    const float* W2r = (const float*)d_in[7];
    float* out = (float*)d_out;

    int E = in_sizes[1] / 2;

    void* p_cnt;
    cudaGetSymbolAddress(&p_cnt, g_cnt);

    cudaFuncSetAttribute(gemm1_kernel,
                         cudaFuncAttributeMaxDynamicSharedMemorySize, G1_SMEM);
    cudaFuncSetAttribute(gemm2_kernel,
                         cudaFuncAttributeMaxDynamicSharedMemorySize, G2_SMEM);

    cudaMemsetAsync(p_cnt, 0, (size_t)NN * sizeof(int));

    detect_kernel<<<1, 512>>>((const int*)ei, E);
    roundx_kernel<<<(NN * D / 4 + 255) / 256, 256>>>(x);
    prepw_kernel<<<(256 * 128 + 128 * 128 + 255) / 256, 256>>>(W1l, W1r, W2l, W2r);
    fill_kernel<<<((E + 1) / 2 + 255) / 256, 256>>>(ei, E);

    agg1_kernel<<<(NN * 32 + 255) / 256, 256>>>();

    gemm1_kernel<<<NTILES * 2, 256, G1_SMEM>>>(b1);
    gemm2_kernel<<<NTILES * 2, 256, G2_SMEM>>>(b2);

    agg2_kernel<<<(NN * 32 + 255) / 256, 256>>>(out);
}

// round 11
// speedup vs baseline: 1.1166x; 1.0490x over previous
#include <cuda_runtime.h>
#include <cuda_fp16.h>
#include <cstdint>

#define NN 50000
#define D  128
#define DO 64
#define CAP 128

__device__ float  g_xr  [NN * D];    // x as tf32 bit patterns (GEMM staging)
__device__ __half g_xh  [NN * D];    // x as fp16 (agg1 gather source)
__device__ float  g_agg [NN * D];    // layer-1 neighbor mean (tf32-rounded)
__device__ float  g_h   [NN * D];    // relu(layer-1 out) (tf32-rounded)
__device__ __half g_hlh [NN * DO];   // h @ W2_l as fp16 (agg2 gather source)
__device__ float  g_base[NN * DO];   // h @ W2_r + b2
__device__ int    g_cnt [NN];
__device__ int    g_csr [NN * CAP];
__device__ int    g_idx64;

#define G1_SWK 264
#define G2_SWK 136
__device__ float g_w1t[2][64 * G1_SWK];
__device__ float g_w2t[2][64 * G2_SWK];

// ---------------------------------------------------------------------------
__device__ __forceinline__ uint32_t f2tf32(float f) {
    uint32_t r;
    asm("cvt.rna.tf32.f32 %0, %1;" : "=r"(r) : "f"(f));
    return r;
}

__device__ __forceinline__ void mma_tf32(float& d0, float& d1, float& d2, float& d3,
                                         uint32_t a0, uint32_t a1, uint32_t a2, uint32_t a3,
                                         uint32_t b0, uint32_t b1) {
    asm volatile(
        "mma.sync.aligned.m16n8k8.row.col.f32.tf32.tf32.f32 "
        "{%0,%1,%2,%3}, {%4,%5,%6,%7}, {%8,%9}, {%0,%1,%2,%3};"
        : "+f"(d0), "+f"(d1), "+f"(d2), "+f"(d3)
        : "r"(a0), "r"(a1), "r"(a2), "r"(a3), "r"(b0), "r"(b1));
}

__device__ __forceinline__ void cpasync16(uint32_t saddr, const void* g) {
    asm volatile("cp.async.cg.shared.global [%0], [%1], 16;"
                 :: "r"(saddr), "l"(g) : "memory");
}
#define CP_COMMIT() asm volatile("cp.async.commit_group;" ::: "memory")

__device__ __forceinline__ int kperm(int k) {
    return (k & ~7) + 2 * (k & 3) + ((k >> 2) & 1);
}

__device__ __forceinline__ int load_idx(const void* ei, long long pos) {
    if (g_idx64) return (int)((const long long*)ei)[pos];
    return ((const int*)ei)[pos];
}

// ---------------------------------------------------------------------------
// Fused prologue: round x (tf32 + fp16 mirrors), transform weights,
// zero g_cnt, detect edge dtype. Partitioned by blockIdx.
// ---------------------------------------------------------------------------
#define PB_X   6250                       // NN*D/4 / 256
#define PB_W   (PB_X + 192)               // (256*128 + 128*128)/256
#define PB_Z   (PB_W + 49)                // 12500 int4 / 256
#define PB_TOT (PB_Z + 1)

__global__ void prologue_kernel(const float* __restrict__ x,
                                const int* __restrict__ ei, int E,
                                const float* __restrict__ W1l,
                                const float* __restrict__ W1r,
                                const float* __restrict__ W2l,
                                const float* __restrict__ W2r) {
    int b = blockIdx.x;
    if (b < PB_X) {
        int i = b * 256 + threadIdx.x;           // over NN*D/4
        float4 v = ((const float4*)x)[i];
        ((uint4*)g_xr)[i] = make_uint4(f2tf32(v.x), f2tf32(v.y),
                                       f2tf32(v.z), f2tf32(v.w));
        __half2 h0 = __floats2half2_rn(v.x, v.y);
        __half2 h1 = __floats2half2_rn(v.z, v.w);
        ((uint2*)g_xh)[i] = make_uint2(*(uint32_t*)&h0, *(uint32_t*)&h1);
    } else if (b < PB_W) {
        int i = (b - PB_X) * 256 + threadIdx.x;
        if (i < 256 * 128) {
            int k = i >> 7, n = i & 127;
            float w = (k < 128) ? W1l[k * 128 + n] : W1r[(k - 128) * 128 + n];
            int h = n >> 6, nl = n & 63;
            ((uint32_t*)g_w1t[h])[nl * G1_SWK + kperm(k)] = f2tf32(w);
        } else {
            int j = i - 256 * 128;
            int k = j >> 7, n = j & 127;
            int h = n >> 6, nl = n & 63;
            const float* W = h ? W2r : W2l;
            ((uint32_t*)g_w2t[h])[nl * G2_SWK + kperm(k)] = f2tf32(W[k * 64 + nl]);
        }
    } else if (b < PB_Z) {
        int i = (b - PB_W) * 256 + threadIdx.x;  // over 12500 int4
        if (i < 12500) ((int4*)g_cnt)[i] = make_int4(0, 0, 0, 0);
    } else {
        int n = E < 256 ? E : 256;
        int i = threadIdx.x;
        int nz = (i < n && ei[2 * i + 1] != 0) ? 1 : 0;
        int any = __syncthreads_or(nz);
        if (i == 0) g_idx64 = any ? 0 : 1;
    }
}

// ---------------------------------------------------------------------------
__global__ void fill_kernel(const void* __restrict__ ei, int E) {
    int half = (E + 1) >> 1;
    int e = blockIdx.x * blockDim.x + threadIdx.x;
    if (e >= half) return;
    int src0 = load_idx(ei, e);
    int dst0 = load_idx(ei, (long long)E + e);
    int e2 = e + half;
    if (e2 < E) {
        int src1 = load_idx(ei, e2);
        int dst1 = load_idx(ei, (long long)E + e2);
        int p0 = atomicAdd(&g_cnt[dst0], 1);
        int p1 = atomicAdd(&g_cnt[dst1], 1);
        if (p0 < CAP) g_csr[dst0 * CAP + p0] = src0;
        if (p1 < CAP) g_csr[dst1 * CAP + p1] = src1;
    } else {
        int p0 = atomicAdd(&g_cnt[dst0], 1);
        if (p0 < CAP) g_csr[dst0 * CAP + p0] = src0;
    }
}

// ---------------------------------------------------------------------------
// Aggregation 1: warp per dst; gather fp16 rows, sum fp32 -> g_agg (tf32)
// ---------------------------------------------------------------------------
__global__ void agg1_kernel() {
    int t = blockIdx.x * blockDim.x + threadIdx.x;
    int node = t >> 5;
    if (node >= NN) return;
    int lane = t & 31;
    int deg = g_cnt[node];
    int degc = deg < CAP ? deg : CAP;
    const int* nb = g_csr + (size_t)node * CAP;
    float4 a0 = make_float4(0,0,0,0), a1 = a0, a2 = a0, a3 = a0;

    auto addrow = [&](int src, float4& acc) {
        uint2 u = *((const uint2*)(g_xh + (size_t)src * D) + lane);
        float2 f0 = __half22float2(*(__half2*)&u.x);
        float2 f1 = __half22float2(*(__half2*)&u.y);
        acc.x += f0.x; acc.y += f0.y; acc.z += f1.x; acc.w += f1.y;
    };

    int i = 0;
    for (; i + 4 <= degc; i += 4) {
        int4 s = *(const int4*)(nb + i);
        addrow(s.x, a0); addrow(s.y, a1); addrow(s.z, a2); addrow(s.w, a3);
    }
    for (; i < degc; i++) addrow(nb[i], a0);

    float4 s;
    s.x = (a0.x + a1.x) + (a2.x + a3.x);
    s.y = (a0.y + a1.y) + (a2.y + a3.y);
    s.z = (a0.z + a1.z) + (a2.z + a3.z);
    s.w = (a0.w + a1.w) + (a2.w + a3.w);
    float inv = 1.0f / (float)(deg > 0 ? deg : 1);
    *(uint4*)(g_agg + (size_t)node * D + lane * 4) =
        make_uint4(f2tf32(s.x * inv), f2tf32(s.y * inv),
                   f2tf32(s.z * inv), f2tf32(s.w * inv));
}

#define SA_STR 36
#define NTILES ((NN + 127) / 128)

// ---------------------------------------------------------------------------
// GEMM1: h = relu([agg | xr] @ W1t + b1)  (tile 128 rows x 64 cols)
// ---------------------------------------------------------------------------
#define G1_SMEM ((64 * G1_SWK + 2 * 128 * SA_STR) * 4)

__global__ void __launch_bounds__(256, 2)
gemm1_kernel(const float* __restrict__ b1) {
    extern __shared__ uint32_t smu[];
    uint32_t* sW = smu;
    uint32_t* sA = smu + 64 * G1_SWK;
    const uint32_t sWaddr = (uint32_t)__cvta_generic_to_shared(sW);
    const uint32_t sAaddr = (uint32_t)__cvta_generic_to_shared(sA);

    const int tid  = threadIdx.x;
    const int wid  = tid >> 5;
    const int lane = tid & 31;
    const int gid  = lane >> 2;
    const int tig  = lane & 3;
    const int wm   = wid & 3;
    const int wn   = wid >> 2;
    const int tile = blockIdx.x >> 1;
    const int half = blockIdx.x & 1;
    const int tile_row = tile * 128;

    auto stage = [&](int c, int buf) {
        uint32_t base = sAaddr + (uint32_t)buf * (128 * SA_STR * 4);
#pragma unroll
        for (int i = tid; i < 1024; i += 256) {
            int r = i >> 3, j = i & 7;
            int row = tile_row + r;
            uint32_t daddr = base + (uint32_t)(r * SA_STR + j * 4) * 4;
            if (row < NN) {
                const float* src = (c < 4)
                    ? (g_agg + (size_t)row * D + c * 32 + j * 4)
                    : (g_xr + (size_t)row * D + (c - 4) * 32 + j * 4);
                cpasync16(daddr, src);
            } else {
                asm volatile("st.shared.v4.b32 [%0], {%1,%1,%1,%1};"
                             :: "r"(daddr), "r"(0) : "memory");
            }
        }
        CP_COMMIT();
    };

    stage(0, 0);
    {
        const float* wsrc = g_w1t[half];
        for (int i = tid * 4; i < 64 * G1_SWK; i += 1024)
            cpasync16(sWaddr + (uint32_t)i * 4, wsrc + i);
        CP_COMMIT();
    }

    float acc[2][4][4];
#pragma unroll
    for (int mt = 0; mt < 2; mt++)
#pragma unroll
        for (int nt = 0; nt < 4; nt++)
#pragma unroll
            for (int q = 0; q < 4; q++) acc[mt][nt][q] = 0.f;

    for (int c = 0; c < 8; c++) {
        if (c + 1 < 8) {
            stage(c + 1, (c + 1) & 1);
            asm volatile("cp.async.wait_group 1;" ::: "memory");
        } else {
            asm volatile("cp.async.wait_group 0;" ::: "memory");
        }
        __syncthreads();

        const uint32_t* sAb = sA + (c & 1) * (128 * SA_STR);
#pragma unroll
        for (int ks = 0; ks < 4; ks++) {
            int kk = ks * 8;
            int kg = c * 32 + kk;
            uint2 b[4];
#pragma unroll
            for (int nt = 0; nt < 4; nt++) {
                int n0 = wn * 32 + nt * 8 + gid;
                b[nt] = *(const uint2*)(sW + n0 * G1_SWK + kg + 2 * tig);
            }
            uint32_t a[2][4];
#pragma unroll
            for (int mt = 0; mt < 2; mt++) {
                int m0 = wm * 32 + mt * 16;
                a[mt][0] = sAb[(m0 + gid) * SA_STR + kk + tig];
                a[mt][1] = sAb[(m0 + gid + 8) * SA_STR + kk + tig];
                a[mt][2] = sAb[(m0 + gid) * SA_STR + kk + tig + 4];
                a[mt][3] = sAb[(m0 + gid + 8) * SA_STR + kk + tig + 4];
            }
#pragma unroll
            for (int mt = 0; mt < 2; mt++)
#pragma unroll
                for (int nt = 0; nt < 4; nt++)
                    mma_tf32(acc[mt][nt][0], acc[mt][nt][1],
                             acc[mt][nt][2], acc[mt][nt][3],
                             a[mt][0], a[mt][1], a[mt][2], a[mt][3],
                             b[nt].x, b[nt].y);
        }
        __syncthreads();
    }

#pragma unroll
    for (int mt = 0; mt < 2; mt++) {
#pragma unroll
        for (int nt = 0; nt < 4; nt++) {
            int n0 = half * 64 + wn * 32 + nt * 8 + 2 * tig;
            float bb0 = b1[n0], bb1 = b1[n0 + 1];
            int r0 = tile_row + wm * 32 + mt * 16 + gid;
            if (r0 < NN)
                *(uint2*)(g_h + (size_t)r0 * D + n0) =
                    make_uint2(f2tf32(fmaxf(acc[mt][nt][0] + bb0, 0.f)),
                               f2tf32(fmaxf(acc[mt][nt][1] + bb1, 0.f)));
            if (r0 + 8 < NN)
                *(uint2*)(g_h + (size_t)(r0 + 8) * D + n0) =
                    make_uint2(f2tf32(fmaxf(acc[mt][nt][2] + bb0, 0.f)),
                               f2tf32(fmaxf(acc[mt][nt][3] + bb1, 0.f)));
        }
    }
}

// ---------------------------------------------------------------------------
// GEMM2: half 0: hl(fp16) = h @ W2l ; half 1: base = h @ W2r + b2
// ---------------------------------------------------------------------------
#define G2_SMEM ((64 * G2_SWK + 2 * 128 * SA_STR) * 4)

__global__ void __launch_bounds__(256, 3)
gemm2_kernel(const float* __restrict__ b2) {
    extern __shared__ uint32_t smu[];
    uint32_t* sW = smu;
    uint32_t* sA = smu + 64 * G2_SWK;
    const uint32_t sWaddr = (uint32_t)__cvta_generic_to_shared(sW);
    const uint32_t sAaddr = (uint32_t)__cvta_generic_to_shared(sA);

    const int tid  = threadIdx.x;
    const int wid  = tid >> 5;
    const int lane = tid & 31;
    const int gid  = lane >> 2;
    const int tig  = lane & 3;
    const int wm   = wid & 3;
    const int wn   = wid >> 2;
    const int tile = blockIdx.x >> 1;
    const int half = blockIdx.x & 1;
    const int tile_row = tile * 128;

    auto stage = [&](int c, int buf) {
        uint32_t base = sAaddr + (uint32_t)buf * (128 * SA_STR * 4);
#pragma unroll
        for (int i = tid; i < 1024; i += 256) {
            int r = i >> 3, j = i & 7;
            int row = tile_row + r;
            uint32_t daddr = base + (uint32_t)(r * SA_STR + j * 4) * 4;
            if (row < NN)
                cpasync16(daddr, g_h + (size_t)row * D + c * 32 + j * 4);
            else
                asm volatile("st.shared.v4.b32 [%0], {%1,%1,%1,%1};"
                             :: "r"(daddr), "r"(0) : "memory");
        }
        CP_COMMIT();
    };

    stage(0, 0);
    {
        const float* wsrc = g_w2t[half];
        for (int i = tid * 4; i < 64 * G2_SWK; i += 1024)
            cpasync16(sWaddr + (uint32_t)i * 4, wsrc + i);
        CP_COMMIT();
    }

    float acc[2][4][4];
#pragma unroll
    for (int mt = 0; mt < 2; mt++)
#pragma unroll
        for (int nt = 0; nt < 4; nt++)
#pragma unroll
            for (int q = 0; q < 4; q++) acc[mt][nt][q] = 0.f;

    for (int c = 0; c < 4; c++) {
        if (c + 1 < 4) {
            stage(c + 1, (c + 1) & 1);
            asm volatile("cp.async.wait_group 1;" ::: "memory");
        } else {
            asm volatile("cp.async.wait_group 0;" ::: "memory");
        }
        __syncthreads();

        const uint32_t* sAb = sA + (c & 1) * (128 * SA_STR);
#pragma unroll
        for (int ks = 0; ks < 4; ks++) {
            int kk = ks * 8;
            int kg = c * 32 + kk;
            uint2 b[4];
#pragma unroll
            for (int nt = 0; nt < 4; nt++) {
                int n0 = wn * 32 + nt * 8 + gid;
                b[nt] = *(const uint2*)(sW + n0 * G2_SWK + kg + 2 * tig);
            }
            uint32_t a[2][4];
#pragma unroll
            for (int mt = 0; mt < 2; mt++) {
                int m0 = wm * 32 + mt * 16;
                a[mt][0] = sAb[(m0 + gid) * SA_STR + kk + tig];
                a[mt][1] = sAb[(m0 + gid + 8) * SA_STR + kk + tig];
                a[mt][2] = sAb[(m0 + gid) * SA_STR + kk + tig + 4];
                a[mt][3] = sAb[(m0 + gid + 8) * SA_STR + kk + tig + 4];
            }
#pragma unroll
            for (int mt = 0; mt < 2; mt++)
#pragma unroll
                for (int nt = 0; nt < 4; nt++)
                    mma_tf32(acc[mt][nt][0], acc[mt][nt][1],
                             acc[mt][nt][2], acc[mt][nt][3],
                             a[mt][0], a[mt][1], a[mt][2], a[mt][3],
                             b[nt].x, b[nt].y);
        }
        __syncthreads();
    }

#pragma unroll
    for (int mt = 0; mt < 2; mt++) {
#pragma unroll
        for (int nt = 0; nt < 4; nt++) {
            int n0 = wn * 32 + nt * 8 + 2 * tig;
            int r0 = tile_row + wm * 32 + mt * 16 + gid;
            if (half == 0) {
                if (r0 < NN)
                    *(__half2*)(g_hlh + (size_t)r0 * DO + n0) =
                        __floats2half2_rn(acc[mt][nt][0], acc[mt][nt][1]);
                if (r0 + 8 < NN)
                    *(__half2*)(g_hlh + (size_t)(r0 + 8) * DO + n0) =
                        __floats2half2_rn(acc[mt][nt][2], acc[mt][nt][3]);
            } else {
                float bb0 = b2[n0], bb1 = b2[n0 + 1];
                if (r0 < NN)
                    *(float2*)(g_base + (size_t)r0 * DO + n0) =
                        make_float2(acc[mt][nt][0] + bb0, acc[mt][nt][1] + bb1);
                if (r0 + 8 < NN)
                    *(float2*)(g_base + (size_t)(r0 + 8) * DO + n0) =
                        make_float2(acc[mt][nt][2] + bb0, acc[mt][nt][3] + bb1);
            }
        }
    }
}

// ---------------------------------------------------------------------------
// Aggregation 2 + finish: out = mean_j(hl_fp16[src_j]) + g_base
// ---------------------------------------------------------------------------
__global__ void agg2_kernel(float* __restrict__ out) {
    int t = blockIdx.x * blockDim.x + threadIdx.x;
    int node = t >> 5;
    if (node >= NN) return;
    int lane = t & 31;
    int deg = g_cnt[node];
    int degc = deg < CAP ? deg : CAP;
    const int* nb = g_csr + (size_t)node * CAP;
    float2 a0 = make_float2(0,0), a1 = a0, a2 = a0, a3 = a0;

    auto addrow = [&](int src, float2& acc) {
        uint32_t u = *((const uint32_t*)(g_hlh + (size_t)src * DO) + lane);
        float2 f = __half22float2(*(__half2*)&u);
        acc.x += f.x; acc.y += f.y;
    };

    int i = 0;
    for (; i + 4 <= degc; i += 4) {
        int4 s = *(const int4*)(nb + i);
        addrow(s.x, a0); addrow(s.y, a1); addrow(s.z, a2); addrow(s.w, a3);
    }
    for (; i < degc; i++) addrow(nb[i], a0);

    float2 s = make_float2((a0.x + a1.x) + (a2.x + a3.x),
                           (a0.y + a1.y) + (a2.y + a3.y));
    float inv = 1.0f / (float)(deg > 0 ? deg : 1);
    float2 b = *(const float2*)(g_base + (size_t)node * DO + lane * 2);
    *(float2*)(out + (size_t)node * DO + lane * 2) =
        make_float2(s.x * inv + b.x, s.y * inv + b.y);
}

extern "C" void kernel_launch(void* const* d_in, const int* in_sizes, int n_in,
                              void* d_out, int out_size) {
    const float* x   = (const float*)d_in[0];
    const void*  ei  = d_in[1];
    const float* W1l = (const float*)d_in[2];
    const float* b1  = (const float*)d_in[3];
    const float* W1r = (const float*)d_in[4];
    const float* W2l = (const float*)d_in[5];
    const float* b2  = (const float*)d_in[6];
    const float* W2r = (const float*)d_in[7];
    float* out = (float*)d_out;

    int E = in_sizes[1] / 2;

    cudaFuncSetAttribute(gemm1_kernel,
                         cudaFuncAttributeMaxDynamicSharedMemorySize, G1_SMEM);
    cudaFuncSetAttribute(gemm2_kernel,
                         cudaFuncAttributeMaxDynamicSharedMemorySize, G2_SMEM);

    prologue_kernel<<<PB_TOT, 256>>>(x, (const int*)ei, E, W1l, W1r, W2l, W2r);
    fill_kernel<<<((E + 1) / 2 + 255) / 256, 256>>>(ei, E);

    agg1_kernel<<<(NN * 32 + 255) / 256, 256>>>();

    gemm1_kernel<<<NTILES * 2, 256, G1_SMEM>>>(b1);
    gemm2_kernel<<<NTILES * 2, 256, G2_SMEM>>>(b2);

    agg2_kernel<<<(NN * 32 + 255) / 256, 256>>>(out);
}